// round 1
// baseline (speedup 1.0000x reference)
#include <cuda_runtime.h>

#define MAXTOK 16384

// ---------------- scratch (device globals; no allocation allowed) ----------
__device__ float g_feat45[MAXTOK * 45];
__device__ float g_feat39[MAXTOK * 39];
__device__ float g_h1[MAXTOK * 256];
__device__ float g_h2[MAXTOK * 128];
__device__ float g_E1[20 * 256];
__device__ float g_C1[10 * 256];
__device__ int g_hist[20];
__device__ int g_base[20];
__device__ int g_cursor[20];
__device__ int g_order[MAXTOK];

// ---------------- packed f32x2 helpers -------------------------------------
__device__ __forceinline__ unsigned long long f2pack(float lo, float hi) {
    unsigned long long r;
    asm("mov.b64 %0,{%1,%2};" : "=l"(r) : "f"(lo), "f"(hi));
    return r;
}
__device__ __forceinline__ void f2unpack(unsigned long long v, float& lo, float& hi) {
    asm("mov.b64 {%0,%1},%2;" : "=f"(lo), "=f"(hi) : "l"(v));
}
__device__ __forceinline__ unsigned long long ffma2(unsigned long long a,
                                                    unsigned long long b,
                                                    unsigned long long c) {
    unsigned long long d;
    asm("fma.rn.f32x2 %0,%1,%2,%3;" : "=l"(d) : "l"(a), "l"(b), "l"(c));
    return d;
}

// ---------------- tiny setup kernels ----------------------------------------
__global__ void k_zero() {
    int i = threadIdx.x;
    if (i < 20) { g_hist[i] = 0; g_cursor[i] = 0; }
}

// E1[s][j] = b1[j] + sum_k aa_emb[s][k] * W1[k][j]        (rows 0..127)
// C1[c][j] = (c!=0) * sum_k chain_emb[c][k] * W1[1067+k][j]
__global__ void k_pre(const float* __restrict__ aa_emb,
                      const float* __restrict__ ch_emb,
                      const float* __restrict__ W1,
                      const float* __restrict__ b1) {
    int r = blockIdx.x, j = threadIdx.x;
    if (r < 20) {
        float acc = b1[j];
#pragma unroll 8
        for (int k = 0; k < 128; k++) acc += aa_emb[r * 128 + k] * W1[k * 256 + j];
        g_E1[r * 256 + j] = acc;
    } else {
        int c = r - 20;
        float acc = 0.f;
        if (c != 0) {
#pragma unroll 8
            for (int k = 0; k < 128; k++)
                acc += ch_emb[c * 128 + k] * W1[(1067 + k) * 256 + j];
        }
        g_C1[c * 256 + j] = acc;
    }
}

// per-token features: xyz_local (45) and dihedral encoding (39)
__global__ void k_feat(const float* __restrict__ xyz,
                       const float* __restrict__ ori,
                       const float* __restrict__ dih, int ntok) {
    int t = blockIdx.x * blockDim.x + threadIdx.x;
    if (t >= ntok) return;
    const float* X = xyz + t * 45;
    float ca0 = X[3], ca1 = X[4], ca2 = X[5];   // CA_IDX = 1
    float o[9];
#pragma unroll
    for (int i = 0; i < 9; i++) o[i] = ori[t * 9 + i];
#pragma unroll
    for (int a = 0; a < 15; a++) {
        float rx = X[a * 3 + 0] - ca0;
        float ry = X[a * 3 + 1] - ca1;
        float rz = X[a * 3 + 2] - ca2;
#pragma unroll
        for (int i = 0; i < 3; i++)  // out[a][i] = sum_j O[j][i]*rel[j]  (O^T)
            g_feat45[t * 45 + a * 3 + i] = o[i] * rx + o[3 + i] * ry + o[6 + i] * rz;
    }
    const float fb[6] = {1.f, 2.f, 3.f, 1.f, 0.5f, 1.f / 3.f};
#pragma unroll
    for (int d = 0; d < 3; d++) {
        float x = dih[t * 3 + d];
        int b = t * 39 + d * 13;
        g_feat39[b] = x;
#pragma unroll
        for (int u = 0; u < 6; u++) {
            g_feat39[b + 1 + u] = sinf(fb[u] * x);
            g_feat39[b + 7 + u] = cosf(fb[u] * x);
        }
    }
}

// counting sort by aa type
__global__ void k_hist(const int* __restrict__ seq, int ntok) {
    for (int t = blockIdx.x * blockDim.x + threadIdx.x; t < ntok;
         t += gridDim.x * blockDim.x)
        atomicAdd(&g_hist[seq[t]], 1);
}
__global__ void k_scan() {
    int s = 0;
    for (int i = 0; i < 20; i++) { g_base[i] = s; s += g_hist[i]; }
}
__global__ void k_scatter(const int* __restrict__ seq, int ntok) {
    for (int t = blockIdx.x * blockDim.x + threadIdx.x; t < ntok;
         t += gridDim.x * blockDim.x) {
        int s = seq[t];
        int pos = atomicAdd(&g_cursor[s], 1);
        g_order[g_base[s] + pos] = t;
    }
}

// ---------------- layer 1, dense part: h1pre = E1[s] + C1[c] + dih*Wdih ----
__global__ void __launch_bounds__(128)
k_l1dense(const float* __restrict__ W1, const int* __restrict__ seq,
          const int* __restrict__ cidx, int ntok) {
    __shared__ __align__(16) float Wd[39 * 256];
    __shared__ __align__(16) float fd[80];
    int tid = threadIdx.x;
    for (int i = tid; i < 39 * 256; i += 128) Wd[i] = W1[1028 * 256 + i];
    __syncthreads();
    int j2 = tid * 2;
    for (int t = blockIdx.x; t < ntok; t += gridDim.x) {
        if (tid < 39) {
            float v = g_feat39[t * 39 + tid];
            fd[2 * tid] = v; fd[2 * tid + 1] = v;
        }
        __syncthreads();
        int s = seq[t], c = cidx[t];
        float2 e = *(const float2*)&g_E1[s * 256 + j2];
        float2 cc = *(const float2*)&g_C1[c * 256 + j2];
        unsigned long long acc = f2pack(e.x + cc.x, e.y + cc.y);
#pragma unroll
        for (int k = 0; k < 39; k++) {
            unsigned long long w = *(const unsigned long long*)&Wd[k * 256 + j2];
            unsigned long long f = *(const unsigned long long*)&fd[2 * k];
            acc = ffma2(f, w, acc);
        }
        float lo, hi; f2unpack(acc, lo, hi);
        *(float2*)&g_h1[t * 256 + j2] = make_float2(lo, hi);
        __syncthreads();
    }
}

// ---------------- layer 1, coord part (grouped by aa type), then relu ------
__global__ void __launch_bounds__(128)
k_l1coord(const float* __restrict__ W1) {
    __shared__ __align__(16) float Wc[45 * 256];
    __shared__ __align__(16) float fd[92];
    int s = blockIdx.x;
    int cnt = g_hist[s];
    int start = blockIdx.y * 64;
    if (start >= cnt) return;
    int tid = threadIdx.x;
    const float* src = W1 + (128 + s * 45) * 256;
    for (int i = tid; i < 45 * 256; i += 128) Wc[i] = src[i];
    __syncthreads();
    int n = min(64, cnt - start);
    int j2 = tid * 2;
    int obase = g_base[s] + start;
    for (int tt = 0; tt < n; tt++) {
        int tok = g_order[obase + tt];
        if (tid < 45) {
            float v = g_feat45[tok * 45 + tid];
            fd[2 * tid] = v; fd[2 * tid + 1] = v;
        }
        __syncthreads();
        float2 h = *(const float2*)&g_h1[tok * 256 + j2];
        unsigned long long acc = f2pack(h.x, h.y);
#pragma unroll
        for (int k = 0; k < 45; k++) {
            unsigned long long w = *(const unsigned long long*)&Wc[k * 256 + j2];
            unsigned long long f = *(const unsigned long long*)&fd[2 * k];
            acc = ffma2(f, w, acc);
        }
        float lo, hi; f2unpack(acc, lo, hi);
        *(float2*)&g_h1[tok * 256 + j2] = make_float2(fmaxf(lo, 0.f), fmaxf(hi, 0.f));
        __syncthreads();
    }
}

// ---------------- layer 2: h2 = relu(h1 @ W2 + b2), W2 in smem -------------
// blockDim 256 = 2 half-blocks x 128 output threads; 16 tokens/group,
// token pairs packed for FFMA2. xs stride 18 (even -> 8B aligned, low conflict)
__global__ void __launch_bounds__(256)
k_layer2(const float* __restrict__ W2, const float* __restrict__ b2, int ntok) {
    extern __shared__ __align__(16) float sm[];
    float* Ws = sm;             // 256*128 = 32768 floats
    float* xs = sm + 32768;     // 256*18  =  4608 floats
    int tid = threadIdx.x;
    for (int i = tid; i < 32768; i += 256) Ws[i] = W2[i];
    int j = tid & 127, h = tid >> 7;
    float bj = b2[j];
    int ngrp = ntok >> 4;
    for (int u = blockIdx.x; u < ngrp; u += gridDim.x) {
        int t0 = u * 16;
        __syncthreads();  // prev iteration's readers done
        for (int idx = tid; idx < 4096; idx += 256) {
            int g = idx >> 8, k = idx & 255;
            xs[k * 18 + g] = g_h1[(t0 + g) * 256 + k];
        }
        __syncthreads();
        unsigned long long acc[4];
#pragma unroll
        for (int p = 0; p < 4; p++) acc[p] = f2pack(bj, bj);
#pragma unroll 8
        for (int k = 0; k < 256; k++) {
            float w = Ws[k * 128 + j];
            unsigned long long wd = f2pack(w, w);
            const float* xr = &xs[k * 18 + h * 8];
#pragma unroll
            for (int p = 0; p < 4; p++)
                acc[p] = ffma2(*(const unsigned long long*)&xr[2 * p], wd, acc[p]);
        }
#pragma unroll
        for (int p = 0; p < 4; p++) {
            float lo, hi; f2unpack(acc[p], lo, hi);
            int t = t0 + h * 8 + 2 * p;
            g_h2[t * 128 + j] = fmaxf(lo, 0.f);
            g_h2[(t + 1) * 128 + j] = fmaxf(hi, 0.f);
        }
    }
}

// ---------------- layers 3+4 fused: out = relu(h2@W3+b3) @ W4 + b4 ---------
__global__ void __launch_bounds__(256)
k_layer34(const float* __restrict__ W3, const float* __restrict__ b3,
          const float* __restrict__ W4, const float* __restrict__ b4,
          float* __restrict__ out, int ntok) {
    extern __shared__ __align__(16) float sm[];
    float* Ws3 = sm;                  // 16384
    float* Ws4 = sm + 16384;          // 16384
    float* xs  = sm + 32768;          // 128*18 = 2304
    float* h3  = sm + 32768 + 2304;   // 128*18 = 2304
    int tid = threadIdx.x;
    for (int i = tid; i < 16384; i += 256) { Ws3[i] = W3[i]; Ws4[i] = W4[i]; }
    int j = tid & 127, h = tid >> 7;
    float b3j = b3[j], b4j = b4[j];
    int ngrp = ntok >> 4;
    for (int u = blockIdx.x; u < ngrp; u += gridDim.x) {
        int t0 = u * 16;
        __syncthreads();  // S0: prev L4 done (h3 readers), prev L3 done (xs readers)
        for (int idx = tid; idx < 2048; idx += 256) {
            int g = idx >> 7, k = idx & 127;
            xs[k * 18 + g] = g_h2[(t0 + g) * 128 + k];
        }
        __syncthreads();  // S1: xs ready
        unsigned long long acc[4];
#pragma unroll
        for (int p = 0; p < 4; p++) acc[p] = f2pack(b3j, b3j);
#pragma unroll 8
        for (int k = 0; k < 128; k++) {
            float w = Ws3[k * 128 + j];
            unsigned long long wd = f2pack(w, w);
            const float* xr = &xs[k * 18 + h * 8];
#pragma unroll
            for (int p = 0; p < 4; p++)
                acc[p] = ffma2(*(const unsigned long long*)&xr[2 * p], wd, acc[p]);
        }
#pragma unroll
        for (int p = 0; p < 4; p++) {
            float lo, hi; f2unpack(acc[p], lo, hi);
            *(unsigned long long*)&h3[j * 18 + h * 8 + 2 * p] =
                f2pack(fmaxf(lo, 0.f), fmaxf(hi, 0.f));
        }
        __syncthreads();  // S2: h3 ready
#pragma unroll
        for (int p = 0; p < 4; p++) acc[p] = f2pack(b4j, b4j);
#pragma unroll 8
        for (int k = 0; k < 128; k++) {
            float w = Ws4[k * 128 + j];
            unsigned long long wd = f2pack(w, w);
            const float* xr = &h3[k * 18 + h * 8];
#pragma unroll
            for (int p = 0; p < 4; p++)
                acc[p] = ffma2(*(const unsigned long long*)&xr[2 * p], wd, acc[p]);
        }
#pragma unroll
        for (int p = 0; p < 4; p++) {
            float lo, hi; f2unpack(acc[p], lo, hi);
            int t = t0 + h * 8 + 2 * p;
            out[t * 128 + j] = lo;
            out[(t + 1) * 128 + j] = hi;
        }
    }
}

// ---------------- launch ----------------------------------------------------
extern "C" void kernel_launch(void* const* d_in, const int* in_sizes, int n_in,
                              void* d_out, int out_size) {
    const int*   seq    = (const int*)  d_in[0];
    const float* xyz    = (const float*)d_in[1];
    const float* dih    = (const float*)d_in[2];
    const int*   cidx   = (const int*)  d_in[3];
    const float* ori    = (const float*)d_in[4];
    /* d_in[5] = atom_mask : unused by reference */
    const float* aa_emb = (const float*)d_in[6];
    const float* ch_emb = (const float*)d_in[7];
    const float* W1 = (const float*)d_in[8];
    const float* b1 = (const float*)d_in[9];
    const float* W2 = (const float*)d_in[10];
    const float* b2 = (const float*)d_in[11];
    const float* W3 = (const float*)d_in[12];
    const float* b3 = (const float*)d_in[13];
    const float* W4 = (const float*)d_in[14];
    const float* b4 = (const float*)d_in[15];
    float* out = (float*)d_out;
    int ntok = in_sizes[0];
    if (ntok > MAXTOK) ntok = MAXTOK;

    const int SMEM2  = (32768 + 256 * 18) * 4;                   // 149504 B
    const int SMEM34 = (16384 + 16384 + 2304 + 2304) * 4;        // 149504 B
    cudaFuncSetAttribute(k_layer2, cudaFuncAttributeMaxDynamicSharedMemorySize, SMEM2);
    cudaFuncSetAttribute(k_layer34, cudaFuncAttributeMaxDynamicSharedMemorySize, SMEM34);

    k_zero<<<1, 32>>>();
    k_pre<<<30, 256>>>(aa_emb, ch_emb, W1, b1);
    k_feat<<<(ntok + 127) / 128, 128>>>(xyz, ori, dih, ntok);
    k_hist<<<128, 256>>>(seq, ntok);
    k_scan<<<1, 1>>>();
    k_scatter<<<128, 256>>>(seq, ntok);
    k_l1dense<<<512, 128>>>(W1, seq, cidx, ntok);
    k_l1coord<<<dim3(20, 32), 128>>>(W1);
    k_layer2<<<148, 256, SMEM2>>>(W2, b2, ntok);
    k_layer34<<<148, 256, SMEM34>>>(W3, b3, W4, b4, out, ntok);
}

// round 2
// speedup vs baseline: 1.1986x; 1.1986x over previous
#include <cuda_runtime.h>

#define MAXTOK 16384

// ---------------- scratch (device globals; no allocation allowed) ----------
__device__ float g_feat45[MAXTOK * 45];
__device__ float g_feat39[MAXTOK * 39];
__device__ float g_h1[MAXTOK * 256];   // sorted-token order
__device__ float g_h2[MAXTOK * 128];   // sorted-token order
__device__ float g_E1[20 * 256];
__device__ float g_C1[10 * 256];
__device__ int g_hist[20];
__device__ int g_base[20];
__device__ int g_cursor[20];
__device__ int g_order[MAXTOK];        // sorted pos -> original token

typedef unsigned long long ull;

// ---------------- packed f32x2 helpers -------------------------------------
static __device__ __forceinline__ ull f2pack(float lo, float hi) {
    ull r; asm("mov.b64 %0,{%1,%2};" : "=l"(r) : "f"(lo), "f"(hi)); return r;
}
static __device__ __forceinline__ void f2unpack(ull v, float& lo, float& hi) {
    asm("mov.b64 {%0,%1},%2;" : "=f"(lo), "=f"(hi) : "l"(v));
}
static __device__ __forceinline__ ull ffma2(ull a, ull b, ull c) {
    ull d; asm("fma.rn.f32x2 %0,%1,%2,%3;" : "=l"(d) : "l"(a), "l"(b), "l"(c)); return d;
}
static __device__ __forceinline__ ull fadd2(ull a, ull b) {
    ull d; asm("add.rn.f32x2 %0,%1,%2;" : "=l"(d) : "l"(a), "l"(b)); return d;
}

// ---------------- setup: E1/C1 tables + zero counters -----------------------
// E1[s][j] = b1[j] + sum_k aa_emb[s][k] * W1[k][j]
// C1[c][j] = (c!=0) * sum_k chain_emb[c][k] * W1[1067+k][j]
__global__ void k_pre(const float* __restrict__ aa_emb,
                      const float* __restrict__ ch_emb,
                      const float* __restrict__ W1,
                      const float* __restrict__ b1) {
    int r = blockIdx.x, j = threadIdx.x;
    if (r == 0 && j < 20) { g_hist[j] = 0; g_cursor[j] = 0; }
    if (r < 20) {
        float acc = b1[j];
#pragma unroll 8
        for (int k = 0; k < 128; k++) acc += aa_emb[r * 128 + k] * W1[k * 256 + j];
        g_E1[r * 256 + j] = acc;
    } else {
        int c = r - 20;
        float acc = 0.f;
        if (c != 0) {
#pragma unroll 8
            for (int k = 0; k < 128; k++)
                acc += ch_emb[c * 128 + k] * W1[(1067 + k) * 256 + j];
        }
        g_C1[c * 256 + j] = acc;
    }
}

// ---------------- per-token features + histogram -----------------------------
__global__ void k_feat(const float* __restrict__ xyz,
                       const float* __restrict__ ori,
                       const float* __restrict__ dih,
                       const int* __restrict__ seq, int ntok) {
    int t = blockIdx.x * blockDim.x + threadIdx.x;
    if (t >= ntok) return;
    const float* X = xyz + t * 45;
    float ca0 = X[3], ca1 = X[4], ca2 = X[5];   // CA_IDX = 1
    float o[9];
#pragma unroll
    for (int i = 0; i < 9; i++) o[i] = ori[t * 9 + i];
#pragma unroll
    for (int a = 0; a < 15; a++) {
        float rx = X[a * 3 + 0] - ca0;
        float ry = X[a * 3 + 1] - ca1;
        float rz = X[a * 3 + 2] - ca2;
#pragma unroll
        for (int i = 0; i < 3; i++)  // O^T @ rel
            g_feat45[t * 45 + a * 3 + i] = o[i] * rx + o[3 + i] * ry + o[6 + i] * rz;
    }
    const float fb[6] = {1.f, 2.f, 3.f, 1.f, 0.5f, 1.f / 3.f};
#pragma unroll
    for (int d = 0; d < 3; d++) {
        float x = dih[t * 3 + d];
        int b = t * 39 + d * 13;
        g_feat39[b] = x;
#pragma unroll
        for (int u = 0; u < 6; u++) {
            g_feat39[b + 1 + u] = sinf(fb[u] * x);
            g_feat39[b + 7 + u] = cosf(fb[u] * x);
        }
    }
    atomicAdd(&g_hist[seq[t]], 1);
}

__global__ void k_scan() {
    int s = 0;
    for (int i = 0; i < 20; i++) { g_base[i] = s; s += g_hist[i]; }
}
__global__ void k_scatter(const int* __restrict__ seq, int ntok) {
    for (int t = blockIdx.x * blockDim.x + threadIdx.x; t < ntok;
         t += gridDim.x * blockDim.x) {
        int s = seq[t];
        int pos = atomicAdd(&g_cursor[s], 1);
        g_order[g_base[s] + pos] = t;
    }
}

// ---------------- layer 1 (merged dense+coord), grouped by aa type -----------
// Block = (type s, slice). K=84 (45 coord + 39 dihedral), J=256, 32 tok/group.
// Thread tile: 4 jpairs x 4 tokens. acc = E1[s] + C1[c] + sum_k W[k]*f[k]; relu.
__global__ void __launch_bounds__(256)
k_l1(const float* __restrict__ W1, const int* __restrict__ cidx) {
    extern __shared__ __align__(16) float sm[];
    float* Ws  = sm;            // 84*256 = 21504
    float* C1s = sm + 21504;    // 10*256 =  2560
    float* E1s = sm + 24064;    // 256
    float* xs  = sm + 24320;    // 84*66  =  5544 (dup pairs, stride 66)
    int tid = threadIdx.x;
    int s = blockIdx.x;
    for (int i = tid; i < 84 * 256; i += 256) {
        int row = i >> 8, col = i & 255;
        int src = (row < 45) ? (128 + s * 45 + row) : (1028 + row - 45);
        Ws[i] = W1[src * 256 + col];
    }
    for (int i = tid; i < 2560; i += 256) C1s[i] = g_C1[i];
    E1s[tid] = g_E1[s * 256 + tid];
    __syncthreads();

    int cnt = g_hist[s], base = g_base[s];
    int start = (cnt * blockIdx.y) >> 3;
    int end   = (cnt * (blockIdx.y + 1)) >> 3;
    int lane = tid & 31, tg = tid >> 5;

    ull e[4];
#pragma unroll
    for (int p = 0; p < 4; p++) e[p] = *(const ull*)&E1s[(lane + 32 * p) * 2];

    for (int g0 = start; g0 < end; g0 += 32) {
        int n = min(32, end - g0);
        __syncthreads();  // prev group's xs readers done
        for (int idx = tid; idx < 84 * 32; idx += 256) {
            int t = idx / 84, k = idx - t * 84;
            float v = 0.f;
            if (t < n) {
                int tok = g_order[base + g0 + t];
                v = (k < 45) ? g_feat45[tok * 45 + k] : g_feat39[tok * 39 + (k - 45)];
            }
            *(ull*)&xs[k * 66 + 2 * t] = f2pack(v, v);
        }
        __syncthreads();
        int cc[4];
#pragma unroll
        for (int q = 0; q < 4; q++) {
            int t = tg * 4 + q;
            int spos = base + g0 + min(t, n - 1);
            cc[q] = cidx[g_order[spos]];
        }
        ull acc[4][4];
#pragma unroll
        for (int p = 0; p < 4; p++)
#pragma unroll
            for (int q = 0; q < 4; q++)
                acc[p][q] = fadd2(e[p], *(const ull*)&C1s[cc[q] * 256 + (lane + 32 * p) * 2]);
#pragma unroll 4
        for (int k = 0; k < 84; k++) {
            ull w[4], x[4];
#pragma unroll
            for (int p = 0; p < 4; p++) w[p] = *(const ull*)&Ws[k * 256 + (lane + 32 * p) * 2];
#pragma unroll
            for (int q = 0; q < 4; q++) x[q] = *(const ull*)&xs[k * 66 + (tg * 4 + q) * 2];
#pragma unroll
            for (int p = 0; p < 4; p++)
#pragma unroll
                for (int q = 0; q < 4; q++)
                    acc[p][q] = ffma2(x[q], w[p], acc[p][q]);
        }
#pragma unroll
        for (int q = 0; q < 4; q++) {
            int t = tg * 4 + q;
            if (t < n) {
                int spos = base + g0 + t;
#pragma unroll
                for (int p = 0; p < 4; p++) {
                    float lo, hi; f2unpack(acc[p][q], lo, hi);
                    *(float2*)&g_h1[spos * 256 + (lane + 32 * p) * 2] =
                        make_float2(fmaxf(lo, 0.f), fmaxf(hi, 0.f));
                }
            }
        }
    }
}

// ---------------- layer 2: h2 = relu(h1 @ W2 + b2) ---------------------------
// K=256, J=128; 32 tok/group; thread tile 2 jpairs x 4 tokens.
__global__ void __launch_bounds__(256)
k_l2(const float* __restrict__ W2, const float* __restrict__ b2, int ntok) {
    extern __shared__ __align__(16) float sm[];
    float* Ws = sm;            // 256*128 = 32768
    float* xs = sm + 32768;    // 256*66  = 16896
    int tid = threadIdx.x;
    for (int i = tid; i < 32768; i += 256) Ws[i] = W2[i];
    int lane = tid & 31, tg = tid >> 5;
    ull bb[2];
#pragma unroll
    for (int p = 0; p < 2; p++) {
        int j2 = (lane + 32 * p) * 2;
        bb[p] = f2pack(b2[j2], b2[j2 + 1]);
    }
    int ngrp = (ntok + 31) >> 5;
    for (int u = blockIdx.x; u < ngrp; u += gridDim.x) {
        int t0 = u * 32, n = min(32, ntok - t0);
        __syncthreads();
        for (int idx = tid; idx < 8192; idx += 256) {
            int t = idx >> 8, k = idx & 255;
            float v = (t < n) ? g_h1[(t0 + t) * 256 + k] : 0.f;
            *(ull*)&xs[k * 66 + 2 * t] = f2pack(v, v);
        }
        __syncthreads();
        ull acc[2][4];
#pragma unroll
        for (int p = 0; p < 2; p++)
#pragma unroll
            for (int q = 0; q < 4; q++) acc[p][q] = bb[p];
#pragma unroll 8
        for (int k = 0; k < 256; k++) {
            ull w[2], x[4];
            w[0] = *(const ull*)&Ws[k * 128 + lane * 2];
            w[1] = *(const ull*)&Ws[k * 128 + lane * 2 + 64];
#pragma unroll
            for (int q = 0; q < 4; q++) x[q] = *(const ull*)&xs[k * 66 + (tg * 4 + q) * 2];
#pragma unroll
            for (int p = 0; p < 2; p++)
#pragma unroll
                for (int q = 0; q < 4; q++)
                    acc[p][q] = ffma2(x[q], w[p], acc[p][q]);
        }
#pragma unroll
        for (int q = 0; q < 4; q++) {
            int t = tg * 4 + q;
            if (t < n) {
#pragma unroll
                for (int p = 0; p < 2; p++) {
                    float lo, hi; f2unpack(acc[p][q], lo, hi);
                    *(float2*)&g_h2[(t0 + t) * 128 + (lane + 32 * p) * 2] =
                        make_float2(fmaxf(lo, 0.f), fmaxf(hi, 0.f));
                }
            }
        }
    }
}

// ---------------- layers 3+4 fused: out = relu(h2@W3+b3)@W4 + b4 -------------
// K=J=128; 32 tok/group; 2 jpairs x 4 tokens; h3 staged duplicated in smem.
__global__ void __launch_bounds__(256)
k_l34(const float* __restrict__ W3, const float* __restrict__ b3,
      const float* __restrict__ W4, const float* __restrict__ b4,
      float* __restrict__ out, int ntok) {
    extern __shared__ __align__(16) float sm[];
    float* W3s = sm;             // 16384
    float* W4s = sm + 16384;     // 16384
    float* xs  = sm + 32768;     // 128*66 = 8448
    float* hs  = sm + 41216;     // 128*66 = 8448
    int tid = threadIdx.x;
    for (int i = tid; i < 16384; i += 256) { W3s[i] = W3[i]; W4s[i] = W4[i]; }
    int lane = tid & 31, tg = tid >> 5;
    ull b3b[2], b4b[2];
#pragma unroll
    for (int p = 0; p < 2; p++) {
        int j2 = (lane + 32 * p) * 2;
        b3b[p] = f2pack(b3[j2], b3[j2 + 1]);
        b4b[p] = f2pack(b4[j2], b4[j2 + 1]);
    }
    int ngrp = (ntok + 31) >> 5;
    for (int u = blockIdx.x; u < ngrp; u += gridDim.x) {
        int t0 = u * 32, n = min(32, ntok - t0);
        __syncthreads();  // prev group's xs/hs readers done
        for (int idx = tid; idx < 4096; idx += 256) {
            int t = idx >> 7, k = idx & 127;
            float v = (t < n) ? g_h2[(t0 + t) * 128 + k] : 0.f;
            *(ull*)&xs[k * 66 + 2 * t] = f2pack(v, v);
        }
        __syncthreads();
        ull acc[2][4];
#pragma unroll
        for (int p = 0; p < 2; p++)
#pragma unroll
            for (int q = 0; q < 4; q++) acc[p][q] = b3b[p];
#pragma unroll 8
        for (int k = 0; k < 128; k++) {
            ull w[2], x[4];
            w[0] = *(const ull*)&W3s[k * 128 + lane * 2];
            w[1] = *(const ull*)&W3s[k * 128 + lane * 2 + 64];
#pragma unroll
            for (int q = 0; q < 4; q++) x[q] = *(const ull*)&xs[k * 66 + (tg * 4 + q) * 2];
#pragma unroll
            for (int p = 0; p < 2; p++)
#pragma unroll
                for (int q = 0; q < 4; q++)
                    acc[p][q] = ffma2(x[q], w[p], acc[p][q]);
        }
        // relu -> stage h3 duplicated
#pragma unroll
        for (int q = 0; q < 4; q++) {
            int t = tg * 4 + q;
#pragma unroll
            for (int p = 0; p < 2; p++) {
                float lo, hi; f2unpack(acc[p][q], lo, hi);
                lo = fmaxf(lo, 0.f); hi = fmaxf(hi, 0.f);
                int j0 = (lane + 32 * p) * 2;
                *(ull*)&hs[j0 * 66 + 2 * t]       = f2pack(lo, lo);
                *(ull*)&hs[(j0 + 1) * 66 + 2 * t] = f2pack(hi, hi);
            }
        }
        __syncthreads();
#pragma unroll
        for (int p = 0; p < 2; p++)
#pragma unroll
            for (int q = 0; q < 4; q++) acc[p][q] = b4b[p];
#pragma unroll 8
        for (int k = 0; k < 128; k++) {
            ull w[2], x[4];
            w[0] = *(const ull*)&W4s[k * 128 + lane * 2];
            w[1] = *(const ull*)&W4s[k * 128 + lane * 2 + 64];
#pragma unroll
            for (int q = 0; q < 4; q++) x[q] = *(const ull*)&hs[k * 66 + (tg * 4 + q) * 2];
#pragma unroll
            for (int p = 0; p < 2; p++)
#pragma unroll
                for (int q = 0; q < 4; q++)
                    acc[p][q] = ffma2(x[q], w[p], acc[p][q]);
        }
#pragma unroll
        for (int q = 0; q < 4; q++) {
            int t = tg * 4 + q;
            if (t < n) {
                int orig = g_order[t0 + t];   // un-sort at the final store
#pragma unroll
                for (int p = 0; p < 2; p++) {
                    float lo, hi; f2unpack(acc[p][q], lo, hi);
                    *(float2*)&out[orig * 128 + (lane + 32 * p) * 2] = make_float2(lo, hi);
                }
            }
        }
    }
}

// ---------------- launch ----------------------------------------------------
extern "C" void kernel_launch(void* const* d_in, const int* in_sizes, int n_in,
                              void* d_out, int out_size) {
    const int*   seq    = (const int*)  d_in[0];
    const float* xyz    = (const float*)d_in[1];
    const float* dih    = (const float*)d_in[2];
    const int*   cidx   = (const int*)  d_in[3];
    const float* ori    = (const float*)d_in[4];
    /* d_in[5] = atom_mask : unused by reference */
    const float* aa_emb = (const float*)d_in[6];
    const float* ch_emb = (const float*)d_in[7];
    const float* W1 = (const float*)d_in[8];
    const float* b1 = (const float*)d_in[9];
    const float* W2 = (const float*)d_in[10];
    const float* b2 = (const float*)d_in[11];
    const float* W3 = (const float*)d_in[12];
    const float* b3 = (const float*)d_in[13];
    const float* W4 = (const float*)d_in[14];
    const float* b4 = (const float*)d_in[15];
    float* out = (float*)d_out;
    int ntok = in_sizes[0];
    if (ntok > MAXTOK) ntok = MAXTOK;

    const int SMEM1  = (84 * 256 + 10 * 256 + 256 + 84 * 66) * 4;           // 119456
    const int SMEM2  = (256 * 128 + 256 * 66) * 4;                          // 198656
    const int SMEM34 = (128 * 128 * 2 + 128 * 66 * 2) * 4;                  // 198656
    cudaFuncSetAttribute(k_l1,  cudaFuncAttributeMaxDynamicSharedMemorySize, SMEM1);
    cudaFuncSetAttribute(k_l2,  cudaFuncAttributeMaxDynamicSharedMemorySize, SMEM2);
    cudaFuncSetAttribute(k_l34, cudaFuncAttributeMaxDynamicSharedMemorySize, SMEM34);

    k_pre<<<30, 256>>>(aa_emb, ch_emb, W1, b1);
    k_feat<<<(ntok + 127) / 128, 128>>>(xyz, ori, dih, seq, ntok);
    k_scan<<<1, 1>>>();
    k_scatter<<<128, 256>>>(seq, ntok);
    k_l1<<<dim3(20, 8), 256, SMEM1>>>(W1, cidx);
    k_l2<<<128, 256, SMEM2>>>(W2, b2, ntok);
    k_l34<<<128, 256, SMEM34>>>(W3, b3, W4, b4, out, ntok);
}

// round 4
// speedup vs baseline: 1.9718x; 1.6452x over previous
#include <cuda_runtime.h>

#define MAXTOK 16384

// ---------------- scratch (device globals; no allocation allowed) ----------
__device__ float g_feat[MAXTOK * 88];   // [tok][88]: 0..44 coord, 45..83 dihedral
__device__ float g_h1[MAXTOK * 256];    // sorted-token order
__device__ float g_h2[MAXTOK * 128];    // sorted-token order
__device__ float g_E1[20 * 256];
__device__ float g_C1[10 * 256];
__device__ int g_hist[20];
__device__ int g_base[20];
__device__ int g_cursor[20];
__device__ int g_order[MAXTOK];         // sorted pos -> original token
__device__ int g_done;

typedef unsigned long long ull;

static __device__ __forceinline__ ull f2pack(float lo, float hi) {
    ull r; asm("mov.b64 %0,{%1,%2};" : "=l"(r) : "f"(lo), "f"(hi)); return r;
}
static __device__ __forceinline__ void f2unpack(ull v, float& lo, float& hi) {
    asm("mov.b64 {%0,%1},%2;" : "=f"(lo), "=f"(hi) : "l"(v));
}
static __device__ __forceinline__ ull ffma2(ull a, ull b, ull c) {
    ull d; asm("fma.rn.f32x2 %0,%1,%2,%3;" : "=l"(d) : "l"(a), "l"(b), "l"(c)); return d;
}
static __device__ __forceinline__ ull fadd2(ull a, ull b) {
    ull d; asm("add.rn.f32x2 %0,%1,%2;" : "=l"(d) : "l"(a), "l"(b)); return d;
}

// ---------------- setup: E1/C1 tables + per-token features + hist + scan ----
__global__ void __launch_bounds__(256)
k_setup(const float* __restrict__ aa_emb, const float* __restrict__ ch_emb,
        const float* __restrict__ W1, const float* __restrict__ b1,
        const float* __restrict__ xyz, const float* __restrict__ ori,
        const float* __restrict__ dih, const int* __restrict__ seq,
        int ntok, int nfeatblk) {
    int b = blockIdx.x, tid = threadIdx.x;
    if (b < 30) {  // precompute E1 / C1
        int j = tid;
        if (b < 20) {
            float acc = b1[j];
#pragma unroll 8
            for (int k = 0; k < 128; k++) acc += aa_emb[b * 128 + k] * W1[k * 256 + j];
            g_E1[b * 256 + j] = acc;
        } else {
            int c = b - 20;
            float acc = 0.f;
            if (c != 0) {
#pragma unroll 8
                for (int k = 0; k < 128; k++)
                    acc += ch_emb[c * 128 + k] * W1[(1067 + k) * 256 + j];
            }
            g_C1[c * 256 + j] = acc;
        }
        return;
    }
    int t = (b - 30) * 256 + tid;
    if (t < ntok) {
        const float* X = xyz + t * 45;
        float ca0 = X[3], ca1 = X[4], ca2 = X[5];   // CA_IDX = 1
        float o[9];
#pragma unroll
        for (int i = 0; i < 9; i++) o[i] = ori[t * 9 + i];
        float* F = g_feat + t * 88;
#pragma unroll
        for (int a = 0; a < 15; a++) {
            float rx = X[a * 3 + 0] - ca0;
            float ry = X[a * 3 + 1] - ca1;
            float rz = X[a * 3 + 2] - ca2;
#pragma unroll
            for (int i = 0; i < 3; i++)  // O^T @ rel
                F[a * 3 + i] = o[i] * rx + o[3 + i] * ry + o[6 + i] * rz;
        }
        const float fb[6] = {1.f, 2.f, 3.f, 1.f, 0.5f, 1.f / 3.f};
#pragma unroll
        for (int d = 0; d < 3; d++) {
            float x = dih[t * 3 + d];
            int bo = 45 + d * 13;
            F[bo] = x;
#pragma unroll
            for (int u = 0; u < 6; u++) {
                F[bo + 1 + u] = sinf(fb[u] * x);
                F[bo + 7 + u] = cosf(fb[u] * x);
            }
        }
        atomicAdd(&g_hist[seq[t]], 1);
    }
    __syncthreads();
    if (tid == 0) {
        __threadfence();
        if (atomicAdd(&g_done, 1) == nfeatblk - 1) {  // last feat block: scan
            __threadfence();  // acquire: see all blocks' hist updates
            int s = 0;
            for (int i = 0; i < 20; i++) {
                int h = atomicAdd(&g_hist[i], 0);
                g_base[i] = s; s += h;
            }
            atomicExch(&g_done, 0);  // reset for next replay
        }
    }
}

// ---------------- block-aggregated counting-sort scatter ---------------------
__global__ void __launch_bounds__(256)
k_scatter(const int* __restrict__ seq, int ntok) {
    __shared__ int lh[20], lb[20], lc[20];
    int tid = threadIdx.x;
    if (tid < 20) { lh[tid] = 0; lc[tid] = 0; }
    __syncthreads();
    int t = blockIdx.x * 256 + tid;
    int s = -1;
    if (t < ntok) { s = seq[t]; atomicAdd(&lh[s], 1); }
    __syncthreads();
    if (tid < 20 && lh[tid] > 0) lb[tid] = atomicAdd(&g_cursor[tid], lh[tid]);
    __syncthreads();
    if (t < ntok) {
        int p = atomicAdd(&lc[s], 1);
        g_order[g_base[s] + lb[s] + p] = t;
    }
}

// ---------------- layer 1 (dense+coord merged), grouped by aa type -----------
// grid (20, 7); 512 thr; K=84, J=256; 64 tokens/group; token-paired FFMA2.
__global__ void __launch_bounds__(512)
k_l1(const float* __restrict__ W1, const int* __restrict__ cidx) {
    extern __shared__ __align__(16) float sm[];
    float* Ws  = sm;            // 84*256 = 21504
    float* C1s = sm + 21504;    // 2560
    float* E1s = sm + 24064;    // 256
    float* xs  = sm + 24320;    // 84*68 = 5712
    int*   cs  = (int*)(sm + 30032);  // 64 ints
    int tid = threadIdx.x, s = blockIdx.x;
    if (s == 0 && blockIdx.y == 0 && tid < 20) g_cursor[tid] = 0;  // for next replay
    for (int i = tid; i < 84 * 256; i += 512) {
        int r = i >> 8, c = i & 255;
        int src = (r < 45) ? (128 + s * 45 + r) : (1028 + r - 45);
        Ws[i] = W1[src * 256 + c];
    }
    for (int i = tid; i < 2560; i += 512) C1s[i] = g_C1[i];
    if (tid < 256) E1s[tid] = g_E1[s * 256 + tid];
    __syncthreads();

    int cnt = g_hist[s], base = g_base[s];
    int st = cnt * blockIdx.y / 7, en = cnt * (blockIdx.y + 1) / 7;
    int lane = tid & 31, w = tid >> 5;
    int jq = w & 3, th = w >> 2;
    int j0 = jq * 64 + lane, j1 = j0 + 32, T0 = th * 16;
    ull e0 = f2pack(E1s[j0], E1s[j0]);
    ull e1 = f2pack(E1s[j1], E1s[j1]);

    for (int g0 = st; g0 < en; g0 += 64) {
        int n = min(64, en - g0);
        __syncthreads();
        {   // stage features (transposed, non-duplicated)
            int t = tid >> 3, seg = tid & 7;
            if (tid < 64) cs[tid] = (tid < n) ? cidx[g_order[base + g0 + tid]] : 0;
            if (t < n) {
                const float4* Fp = (const float4*)(g_feat + (size_t)g_order[base + g0 + t] * 88);
                for (int c = seg; c < 21; c += 8) {
                    float4 v = Fp[c]; int k = 4 * c;
                    xs[k * 68 + t] = v.x; xs[(k + 1) * 68 + t] = v.y;
                    xs[(k + 2) * 68 + t] = v.z; xs[(k + 3) * 68 + t] = v.w;
                }
            } else {
                for (int c = seg; c < 21; c += 8) {
                    int k = 4 * c;
                    xs[k * 68 + t] = 0.f; xs[(k + 1) * 68 + t] = 0.f;
                    xs[(k + 2) * 68 + t] = 0.f; xs[(k + 3) * 68 + t] = 0.f;
                }
            }
        }
        __syncthreads();
        ull a0[8], a1[8];
#pragma unroll
        for (int u = 0; u < 8; u++) {
            int ca = cs[T0 + 2 * u], cb = cs[T0 + 2 * u + 1];
            a0[u] = fadd2(e0, f2pack(C1s[ca * 256 + j0], C1s[cb * 256 + j0]));
            a1[u] = fadd2(e1, f2pack(C1s[ca * 256 + j1], C1s[cb * 256 + j1]));
        }
#pragma unroll 4
        for (int k = 0; k < 84; k++) {
            float w0 = Ws[k * 256 + j0], w1 = Ws[k * 256 + j1];
            ull wd0 = f2pack(w0, w0), wd1 = f2pack(w1, w1);
            const ulonglong2* xr = (const ulonglong2*)&xs[k * 68 + T0];
            ulonglong2 xa = xr[0], xb = xr[1], xc = xr[2], xd = xr[3];
            a0[0] = ffma2(xa.x, wd0, a0[0]); a1[0] = ffma2(xa.x, wd1, a1[0]);
            a0[1] = ffma2(xa.y, wd0, a0[1]); a1[1] = ffma2(xa.y, wd1, a1[1]);
            a0[2] = ffma2(xb.x, wd0, a0[2]); a1[2] = ffma2(xb.x, wd1, a1[2]);
            a0[3] = ffma2(xb.y, wd0, a0[3]); a1[3] = ffma2(xb.y, wd1, a1[3]);
            a0[4] = ffma2(xc.x, wd0, a0[4]); a1[4] = ffma2(xc.x, wd1, a1[4]);
            a0[5] = ffma2(xc.y, wd0, a0[5]); a1[5] = ffma2(xc.y, wd1, a1[5]);
            a0[6] = ffma2(xd.x, wd0, a0[6]); a1[6] = ffma2(xd.x, wd1, a1[6]);
            a0[7] = ffma2(xd.y, wd0, a0[7]); a1[7] = ffma2(xd.y, wd1, a1[7]);
        }
#pragma unroll
        for (int u = 0; u < 8; u++) {
            int ta = T0 + 2 * u;
            if (ta < n) {
                int pa = (base + g0 + ta) * 256;
                float va0, vb0, va1, vb1;
                f2unpack(a0[u], va0, vb0);
                f2unpack(a1[u], va1, vb1);
                g_h1[pa + j0] = fmaxf(va0, 0.f);
                g_h1[pa + j1] = fmaxf(va1, 0.f);
                if (ta + 1 < n) {
                    g_h1[pa + 256 + j0] = fmaxf(vb0, 0.f);
                    g_h1[pa + 256 + j1] = fmaxf(vb1, 0.f);
                }
            }
        }
    }
}

// ---------------- layer 2: h2 = relu(h1 @ W2 + b2) ---------------------------
// 512 thr; K=256, J=128; 64 tokens/group; token-paired FFMA2.
__global__ void __launch_bounds__(512)
k_l2(const float* __restrict__ W2, const float* __restrict__ b2, int ntok) {
    extern __shared__ __align__(16) float sm[];
    float* Ws = sm;            // 256*128 = 32768
    float* xs = sm + 32768;    // 256*68  = 17408
    int tid = threadIdx.x;
    if (blockIdx.x == 0 && tid < 20) g_hist[tid] = 0;  // for next replay
    for (int i = tid; i < 32768; i += 512) Ws[i] = W2[i];
    int lane = tid & 31, w = tid >> 5;
    int jh = w & 1, to = w >> 1;
    int j0 = jh * 64 + lane, j1 = j0 + 32, T0 = to * 8;
    ull bb0 = f2pack(b2[j0], b2[j0]), bb1 = f2pack(b2[j1], b2[j1]);
    int ngrp = (ntok + 63) >> 6;
    for (int u = blockIdx.x; u < ngrp; u += gridDim.x) {
        int t0 = u * 64;
        __syncthreads();
        {
            int t = tid >> 3, seg = tid & 7;
            int gt = t0 + t;
            if (gt < ntok) {
                const float4* H = (const float4*)(g_h1 + (size_t)gt * 256);
                for (int c = seg; c < 64; c += 8) {
                    float4 v = H[c]; int k = 4 * c;
                    xs[k * 68 + t] = v.x; xs[(k + 1) * 68 + t] = v.y;
                    xs[(k + 2) * 68 + t] = v.z; xs[(k + 3) * 68 + t] = v.w;
                }
            } else {
                for (int c = seg; c < 64; c += 8) {
                    int k = 4 * c;
                    xs[k * 68 + t] = 0.f; xs[(k + 1) * 68 + t] = 0.f;
                    xs[(k + 2) * 68 + t] = 0.f; xs[(k + 3) * 68 + t] = 0.f;
                }
            }
        }
        __syncthreads();
        ull a0[4], a1[4];
#pragma unroll
        for (int p = 0; p < 4; p++) { a0[p] = bb0; a1[p] = bb1; }
#pragma unroll 4
        for (int k = 0; k < 256; k++) {
            float w0 = Ws[k * 128 + j0], w1 = Ws[k * 128 + j1];
            ull wd0 = f2pack(w0, w0), wd1 = f2pack(w1, w1);
            const ulonglong2* xr = (const ulonglong2*)&xs[k * 68 + T0];
            ulonglong2 xa = xr[0], xb = xr[1];
            a0[0] = ffma2(xa.x, wd0, a0[0]); a1[0] = ffma2(xa.x, wd1, a1[0]);
            a0[1] = ffma2(xa.y, wd0, a0[1]); a1[1] = ffma2(xa.y, wd1, a1[1]);
            a0[2] = ffma2(xb.x, wd0, a0[2]); a1[2] = ffma2(xb.x, wd1, a1[2]);
            a0[3] = ffma2(xb.y, wd0, a0[3]); a1[3] = ffma2(xb.y, wd1, a1[3]);
        }
#pragma unroll
        for (int p = 0; p < 4; p++) {
            int ta = t0 + T0 + 2 * p;
            if (ta < ntok) {
                float va0, vb0, va1, vb1;
                f2unpack(a0[p], va0, vb0);
                f2unpack(a1[p], va1, vb1);
                g_h2[ta * 128 + j0] = fmaxf(va0, 0.f);
                g_h2[ta * 128 + j1] = fmaxf(va1, 0.f);
                if (ta + 1 < ntok) {
                    g_h2[(ta + 1) * 128 + j0] = fmaxf(vb0, 0.f);
                    g_h2[(ta + 1) * 128 + j1] = fmaxf(vb1, 0.f);
                }
            }
        }
    }
}

// ---------------- layers 3+4 fused ------------------------------------------
__global__ void __launch_bounds__(512)
k_l34(const float* __restrict__ W3, const float* __restrict__ b3,
      const float* __restrict__ W4, const float* __restrict__ b4,
      float* __restrict__ out, int ntok) {
    extern __shared__ __align__(16) float sm[];
    float* W3s = sm;              // 16384
    float* W4s = sm + 16384;      // 16384
    float* xs  = sm + 32768;      // 128*68 = 8704
    float* hs  = sm + 41472;      // 128*68 = 8704
    int*   os  = (int*)(sm + 50176);  // 64 ints
    int tid = threadIdx.x;
    for (int i = tid; i < 16384; i += 512) { W3s[i] = W3[i]; W4s[i] = W4[i]; }
    int lane = tid & 31, w = tid >> 5;
    int jh = w & 1, to = w >> 1;
    int j0 = jh * 64 + lane, j1 = j0 + 32, T0 = to * 8;
    ull b30 = f2pack(b3[j0], b3[j0]), b31 = f2pack(b3[j1], b3[j1]);
    ull b40 = f2pack(b4[j0], b4[j0]), b41 = f2pack(b4[j1], b4[j1]);
    int ngrp = (ntok + 63) >> 6;
    for (int u = blockIdx.x; u < ngrp; u += gridDim.x) {
        int t0 = u * 64;
        __syncthreads();
        {
            int t = tid >> 3, seg = tid & 7;
            int gt = t0 + t;
            if (tid < 64) os[tid] = (t0 + tid < ntok) ? g_order[t0 + tid] : 0;
            if (gt < ntok) {
                const float4* H = (const float4*)(g_h2 + (size_t)gt * 128);
                for (int c = seg; c < 32; c += 8) {
                    float4 v = H[c]; int k = 4 * c;
                    xs[k * 68 + t] = v.x; xs[(k + 1) * 68 + t] = v.y;
                    xs[(k + 2) * 68 + t] = v.z; xs[(k + 3) * 68 + t] = v.w;
                }
            } else {
                for (int c = seg; c < 32; c += 8) {
                    int k = 4 * c;
                    xs[k * 68 + t] = 0.f; xs[(k + 1) * 68 + t] = 0.f;
                    xs[(k + 2) * 68 + t] = 0.f; xs[(k + 3) * 68 + t] = 0.f;
                }
            }
        }
        __syncthreads();
        // ---- L3 ----
        ull a0[4], a1[4];
#pragma unroll
        for (int p = 0; p < 4; p++) { a0[p] = b30; a1[p] = b31; }
#pragma unroll 4
        for (int k = 0; k < 128; k++) {
            float w0 = W3s[k * 128 + j0], w1 = W3s[k * 128 + j1];
            ull wd0 = f2pack(w0, w0), wd1 = f2pack(w1, w1);
            const ulonglong2* xr = (const ulonglong2*)&xs[k * 68 + T0];
            ulonglong2 xa = xr[0], xb = xr[1];
            a0[0] = ffma2(xa.x, wd0, a0[0]); a1[0] = ffma2(xa.x, wd1, a1[0]);
            a0[1] = ffma2(xa.y, wd0, a0[1]); a1[1] = ffma2(xa.y, wd1, a1[1]);
            a0[2] = ffma2(xb.x, wd0, a0[2]); a1[2] = ffma2(xb.x, wd1, a1[2]);
            a0[3] = ffma2(xb.y, wd0, a0[3]); a1[3] = ffma2(xb.y, wd1, a1[3]);
        }
#pragma unroll
        for (int p = 0; p < 4; p++) {
            float va0, vb0, va1, vb1;
            f2unpack(a0[p], va0, vb0);
            f2unpack(a1[p], va1, vb1);
            *(ull*)&hs[j0 * 68 + T0 + 2 * p] = f2pack(fmaxf(va0, 0.f), fmaxf(vb0, 0.f));
            *(ull*)&hs[j1 * 68 + T0 + 2 * p] = f2pack(fmaxf(va1, 0.f), fmaxf(vb1, 0.f));
        }
        __syncthreads();
        // ---- L4 ----
#pragma unroll
        for (int p = 0; p < 4; p++) { a0[p] = b40; a1[p] = b41; }
#pragma unroll 4
        for (int k = 0; k < 128; k++) {
            float w0 = W4s[k * 128 + j0], w1 = W4s[k * 128 + j1];
            ull wd0 = f2pack(w0, w0), wd1 = f2pack(w1, w1);
            const ulonglong2* xr = (const ulonglong2*)&hs[k * 68 + T0];
            ulonglong2 xa = xr[0], xb = xr[1];
            a0[0] = ffma2(xa.x, wd0, a0[0]); a1[0] = ffma2(xa.x, wd1, a1[0]);
            a0[1] = ffma2(xa.y, wd0, a0[1]); a1[1] = ffma2(xa.y, wd1, a1[1]);
            a0[2] = ffma2(xb.x, wd0, a0[2]); a1[2] = ffma2(xb.x, wd1, a1[2]);
            a0[3] = ffma2(xb.y, wd0, a0[3]); a1[3] = ffma2(xb.y, wd1, a1[3]);
        }
#pragma unroll
        for (int p = 0; p < 4; p++) {
            int ta = T0 + 2 * p;
            if (t0 + ta < ntok) {
                float va0, vb0, va1, vb1;
                f2unpack(a0[p], va0, vb0);
                f2unpack(a1[p], va1, vb1);
                int oa = os[ta];
                out[oa * 128 + j0] = va0;
                out[oa * 128 + j1] = va1;
                if (t0 + ta + 1 < ntok) {
                    int ob = os[ta + 1];
                    out[ob * 128 + j0] = vb0;
                    out[ob * 128 + j1] = vb1;
                }
            }
        }
    }
}

// ---------------- launch ----------------------------------------------------
extern "C" void kernel_launch(void* const* d_in, const int* in_sizes, int n_in,
                              void* d_out, int out_size) {
    const int*   seq    = (const int*)  d_in[0];
    const float* xyz    = (const float*)d_in[1];
    const float* dih    = (const float*)d_in[2];
    const int*   cidx   = (const int*)  d_in[3];
    const float* ori    = (const float*)d_in[4];
    /* d_in[5] = atom_mask : unused by reference */
    const float* aa_emb = (const float*)d_in[6];
    const float* ch_emb = (const float*)d_in[7];
    const float* W1 = (const float*)d_in[8];
    const float* b1 = (const float*)d_in[9];
    const float* W2 = (const float*)d_in[10];
    const float* b2 = (const float*)d_in[11];
    const float* W3 = (const float*)d_in[12];
    const float* b3 = (const float*)d_in[13];
    const float* W4 = (const float*)d_in[14];
    const float* b4 = (const float*)d_in[15];
    float* out = (float*)d_out;
    int ntok = in_sizes[0];
    if (ntok > MAXTOK) ntok = MAXTOK;

    int nfeatblk = (ntok + 255) / 256;
    const int SMEM1  = (30032 + 64) * 4;              // 120384 B (cs = 64 ints!)
    const int SMEM2  = (32768 + 17408) * 4;           // 200704 B
    const int SMEM34 = (50176 + 64) * 4;              // 200960 B
    cudaFuncSetAttribute(k_l1,  cudaFuncAttributeMaxDynamicSharedMemorySize, SMEM1);
    cudaFuncSetAttribute(k_l2,  cudaFuncAttributeMaxDynamicSharedMemorySize, SMEM2);
    cudaFuncSetAttribute(k_l34, cudaFuncAttributeMaxDynamicSharedMemorySize, SMEM34);

    k_setup<<<30 + nfeatblk, 256>>>(aa_emb, ch_emb, W1, b1, xyz, ori, dih, seq,
                                    ntok, nfeatblk);
    k_scatter<<<(ntok + 255) / 256, 256>>>(seq, ntok);
    k_l1<<<dim3(20, 7), 512, SMEM1>>>(W1, cidx);
    k_l2<<<128, 512, SMEM2>>>(W2, b2, ntok);
    k_l34<<<128, 512, SMEM34>>>(W3, b3, W4, b4, out, ntok);
}